// round 7
// baseline (speedup 1.0000x reference)
#include <cuda_runtime.h>
#include <cuda_bf16.h>
#include <cuda_fp16.h>
#include <cstdint>
#include <cstddef>

#define NN 100000
#define NPAD 100096   // 782 * 128
#define NE 1600000
#define C 128
#define NB_SCAN 98    // ceil(NN / 1024)

// ---------------- scratch (device globals) ----------------
__device__ int   g_deg[NN];
__device__ int   g_ptr[NN + 1];
__device__ int   g_cursor[NN];
__device__ float g_invc[NN];
__device__ int   g_csr[NE];
__device__ int   g_bsum[128];

__device__ __half g_xf16 [(size_t)NPAD * C];
__device__ __half g_h1f16[(size_t)NPAD * C];

__device__ __nv_bfloat16 g_xh [(size_t)NPAD * C];
__device__ __nv_bfloat16 g_xl [(size_t)NPAD * C];
__device__ __nv_bfloat16 g_aggh[(size_t)NPAD * C];
__device__ __nv_bfloat16 g_aggl[(size_t)NPAD * C];
__device__ __nv_bfloat16 g_h1h[(size_t)NPAD * C];
__device__ __nv_bfloat16 g_h1l[(size_t)NPAD * C];
__device__ __nv_bfloat16 g_h2h[(size_t)NPAD * C];
__device__ __nv_bfloat16 g_h2l[(size_t)NPAD * C];

// weights: layer1/layer2 [n=128][k=256] (Wl||Wr), decoder [n=128][k=128]
__device__ __nv_bfloat16 g_w1h[128 * 256], g_w1l[128 * 256];
__device__ __nv_bfloat16 g_w2h[128 * 256], g_w2l[128 * 256];
__device__ __nv_bfloat16 g_wdh[128 * 128], g_wdl[128 * 128];

// ---------------- helpers ----------------
__device__ __forceinline__ uint32_t s2u(const void* p) {
    uint32_t a;
    asm("{ .reg .u64 t; cvta.to.shared.u64 t, %1; cvt.u32.u64 %0, t; }" : "=r"(a) : "l"(p));
    return a;
}
__device__ __forceinline__ void split1(float v, __nv_bfloat16& h, __nv_bfloat16& l) {
    h = __float2bfloat16(v);
    l = __float2bfloat16(v - __bfloat162float(h));
}
__device__ __forceinline__ void ldsm4(uint32_t* r, uint32_t addr) {
    asm volatile("ldmatrix.sync.aligned.m8n8.x4.shared.b16 {%0,%1,%2,%3}, [%4];"
                 : "=r"(r[0]), "=r"(r[1]), "=r"(r[2]), "=r"(r[3]) : "r"(addr));
}
__device__ __forceinline__ void mma16816(float* d, const uint32_t* a, const uint32_t* b) {
    asm volatile(
        "mma.sync.aligned.m16n8k16.row.col.f32.bf16.bf16.f32 "
        "{%0,%1,%2,%3}, {%4,%5,%6,%7}, {%8,%9}, {%0,%1,%2,%3};"
        : "+f"(d[0]), "+f"(d[1]), "+f"(d[2]), "+f"(d[3])
        : "r"(a[0]), "r"(a[1]), "r"(a[2]), "r"(a[3]), "r"(b[0]), "r"(b[1]));
}
__device__ __forceinline__ uint32_t swz64(uint32_t off) {
    return off ^ ((off >> 3) & 0x30u);
}
__device__ __forceinline__ void cp16(uint32_t saddr, const void* gaddr) {
    asm volatile("cp.async.cg.shared.global [%0], [%1], 16;" :: "r"(saddr), "l"(gaddr));
}
__device__ __forceinline__ void acc8(float* a, uint4 v) {
    const __half2* h = (const __half2*)&v;
    #pragma unroll
    for (int q = 0; q < 4; q++) {
        float2 f = __half22float2(h[q]);
        a[2 * q]     += f.x;
        a[2 * q + 1] += f.y;
    }
}

// ---------------- CSR build ----------------
__global__ void count_kernel(const int4* __restrict__ dst4) {
    int i = blockIdx.x * blockDim.x + threadIdx.x;
    if (i < NE / 4) {
        int4 d = dst4[i];
        atomicAdd(&g_deg[d.x], 1);
        atomicAdd(&g_deg[d.y], 1);
        atomicAdd(&g_deg[d.z], 1);
        atomicAdd(&g_deg[d.w], 1);
    }
}
__global__ void scan1_kernel() {
    __shared__ int wsum[32];
    const int lane = threadIdx.x & 31;
    const int wid  = threadIdx.x >> 5;
    int i = blockIdx.x * 1024 + threadIdx.x;
    int v = (i < NN) ? g_deg[i] : 0;
    int incl = v;
    #pragma unroll
    for (int o = 1; o < 32; o <<= 1) {
        int t = __shfl_up_sync(0xFFFFFFFFu, incl, o);
        if (lane >= o) incl += t;
    }
    if (lane == 31) wsum[wid] = incl;
    __syncthreads();
    if (wid == 0) {
        int ws = wsum[lane];
        int wi = ws;
        #pragma unroll
        for (int o = 1; o < 32; o <<= 1) {
            int t = __shfl_up_sync(0xFFFFFFFFu, wi, o);
            if (lane >= o) wi += t;
        }
        wsum[lane] = wi - ws;
    }
    __syncthreads();
    int excl = wsum[wid] + incl - v;
    if (i < NN) g_ptr[i] = excl;
    if (threadIdx.x == 1023) g_bsum[blockIdx.x] = excl + v;
}
__global__ void scan2_kernel() {
    __shared__ int ws[4];
    const int t = threadIdx.x;
    const int lane = t & 31;
    const int wid  = t >> 5;
    int v = (t < NB_SCAN) ? g_bsum[t] : 0;
    int incl = v;
    #pragma unroll
    for (int o = 1; o < 32; o <<= 1) {
        int s = __shfl_up_sync(0xFFFFFFFFu, incl, o);
        if (lane >= o) incl += s;
    }
    if (lane == 31) ws[wid] = incl;
    __syncthreads();
    int add = 0;
    #pragma unroll
    for (int w = 0; w < 4; w++) if (w < wid) add += ws[w];
    int excl = add + incl - v;
    __syncthreads();
    if (t < NB_SCAN) g_bsum[t] = excl;
}
__global__ void scan3_kernel() {
    int i = blockIdx.x * 1024 + threadIdx.x;
    if (i == 0) g_ptr[NN] = NE;
    if (i < NN) {
        g_ptr[i] += g_bsum[blockIdx.x];
        int d = g_deg[i];
        g_invc[i] = 1.0f / (float)(d < 1 ? 1 : d);
        g_cursor[i] = 0;
    }
}
__global__ void build_kernel(const int* __restrict__ src, const int* __restrict__ dst) {
    int e = blockIdx.x * blockDim.x + threadIdx.x;
    if (e < NE) {
        int d   = dst[e];
        int pos = atomicAdd(&g_cursor[d], 1);
        g_csr[g_ptr[d] + pos] = src[e];
    }
}

// ---------------- fp32 -> hi/lo bf16 + fp16 shadow for x ----------------
__global__ void split_kernel(const float* __restrict__ in,
                             __nv_bfloat16* __restrict__ hi,
                             __nv_bfloat16* __restrict__ lo,
                             __half* __restrict__ f16) {
    int i = blockIdx.x * blockDim.x + threadIdx.x;
    if (i < NN * C / 4) {
        float4 v = ((const float4*)in)[i];
        __nv_bfloat162 h01, h23, l01, l23;
        split1(v.x, h01.x, l01.x); split1(v.y, h01.y, l01.y);
        split1(v.z, h23.x, l23.x); split1(v.w, h23.y, l23.y);
        ((__nv_bfloat162*)hi)[i * 2]     = h01;
        ((__nv_bfloat162*)hi)[i * 2 + 1] = h23;
        ((__nv_bfloat162*)lo)[i * 2]     = l01;
        ((__nv_bfloat162*)lo)[i * 2 + 1] = l23;
        ((__half2*)f16)[i * 2]     = __floats2half2_rn(v.x, v.y);
        ((__half2*)f16)[i * 2 + 1] = __floats2half2_rn(v.z, v.w);
    }
}

// ---------------- weight prep: grid (128, 3) ----------------
__global__ void wprep_kernel(const float* __restrict__ W1l, const float* __restrict__ W1r,
                             const float* __restrict__ W2l, const float* __restrict__ W2r,
                             const float* __restrict__ Wd) {
    const int n = blockIdx.x;
    const int which = blockIdx.y;
    const float* Wl; const float* Wr; __nv_bfloat16 *bh, *bl; int K;
    if (which == 0)      { Wl = W1l; Wr = W1r; bh = g_w1h; bl = g_w1l; K = 256; }
    else if (which == 1) { Wl = W2l; Wr = W2r; bh = g_w2h; bl = g_w2l; K = 256; }
    else                 { Wl = Wd;  Wr = nullptr; bh = g_wdh; bl = g_wdl; K = 128; }
    for (int k = threadIdx.x; k < K; k += blockDim.x) {
        float v = (k < C) ? Wl[k * C + n] : Wr[(k - C) * C + n];
        __nv_bfloat16 h, l;
        split1(v, h, l);
        bh[n * K + k] = h;
        bl[n * K + k] = l;
    }
}

// ---------------- aggregation v2: half-warp per edge, 8-edge unroll ----------------
__global__ void agg_kernel(const __half* __restrict__ feat) {
    int gw = (blockIdx.x * blockDim.x + threadIdx.x) >> 5;
    if (gw >= NN) return;
    const int lane = threadIdx.x & 31;
    const int half = lane >> 4;     // which edge of the pair
    const int li   = lane & 15;     // 16 lanes x uint4 = 256B row
    int beg = g_ptr[gw], end = g_ptr[gw + 1];
    float acc[8];
    #pragma unroll
    for (int j = 0; j < 8; j++) acc[j] = 0.f;

    int e = beg;
    for (; e + 8 <= end; e += 8) {
        int i0 = g_csr[e + 0 + half];
        int i1 = g_csr[e + 2 + half];
        int i2 = g_csr[e + 4 + half];
        int i3 = g_csr[e + 6 + half];
        uint4 v0 = *((const uint4*)(feat + (size_t)i0 * C) + li);
        uint4 v1 = *((const uint4*)(feat + (size_t)i1 * C) + li);
        uint4 v2 = *((const uint4*)(feat + (size_t)i2 * C) + li);
        uint4 v3 = *((const uint4*)(feat + (size_t)i3 * C) + li);
        acc8(acc, v0); acc8(acc, v1); acc8(acc, v2); acc8(acc, v3);
    }
    for (; e + 2 <= end; e += 2) {
        int i = g_csr[e + half];
        uint4 v = *((const uint4*)(feat + (size_t)i * C) + li);
        acc8(acc, v);
    }
    if (e < end && half == 0) {
        int i = g_csr[e];
        uint4 v = *((const uint4*)(feat + (size_t)i * C) + li);
        acc8(acc, v);
    }
    #pragma unroll
    for (int j = 0; j < 8; j++)
        acc[j] += __shfl_xor_sync(0xFFFFFFFFu, acc[j], 16);

    const float iv = g_invc[gw];
    __nv_bfloat162 hv[4], lv[4];
    #pragma unroll
    for (int q = 0; q < 4; q++) {
        float a = acc[2 * q] * iv, b = acc[2 * q + 1] * iv;
        split1(a, hv[q].x, lv[q].x);
        split1(b, hv[q].y, lv[q].y);
    }
    __nv_bfloat16* outp = half ? g_aggl : g_aggh;
    const __nv_bfloat162* srcp = half ? lv : hv;
    *((uint4*)(outp + (size_t)gw * C + li * 8)) = *(const uint4*)srcp;
}

// ---------------- cp.async-pipelined split-bf16 GEMM ----------------
// MODE 0: layer1 (K=256: A1=agg, A2=x)  relu(acc+bias) -> fp16 + hi/lo
// MODE 1: layer2 (K=256: A1=agg, A2=h1) relu(acc+bias) -> hi/lo
// MODE 2: decoder (K=128: A1=h2)        alpha*(acc+bias)+(1-alpha)*xres -> f32
template <int MODE>
__global__ __launch_bounds__(256) void gemm_mma_kernel(
    const __nv_bfloat16* __restrict__ A1h, const __nv_bfloat16* __restrict__ A1l,
    const __nv_bfloat16* __restrict__ A2h, const __nv_bfloat16* __restrict__ A2l,
    const __nv_bfloat16* __restrict__ Bh,  const __nv_bfloat16* __restrict__ Bl,
    const float* __restrict__ bias, const float* __restrict__ xres,
    const float* __restrict__ alphaPtr,
    float* __restrict__ outF, __half* __restrict__ outF16,
    __nv_bfloat16* __restrict__ outH, __nv_bfloat16* __restrict__ outL)
{
    constexpr int K   = (MODE == 2) ? 128 : 256;
    constexpr int NCH = K / 32;
    extern __shared__ __align__(128) char smem[];
    const uint32_t us = s2u(smem);

    const int tid  = threadIdx.x;
    const int wid  = tid >> 5;
    const int lane = tid & 31;
    const int m0   = blockIdx.x * 128;
    const int m0w  = (wid >> 1) * 32;
    const int n0w  = (wid & 1) * 64;

    const int lrow = tid >> 1;
    const int c16a = (tid & 1) * 2;

    float acc[2][8][4];
    #pragma unroll
    for (int i = 0; i < 2; i++)
        #pragma unroll
        for (int j = 0; j < 8; j++)
            #pragma unroll
            for (int q = 0; q < 4; q++) acc[i][j][q] = 0.f;

    auto issue = [&](int kc, int buf) {
        const __nv_bfloat16* sAh = (MODE != 2 && kc >= NCH / 2) ? A2h : A1h;
        const __nv_bfloat16* sAl = (MODE != 2 && kc >= NCH / 2) ? A2l : A1l;
        const int aoff = (MODE == 2) ? kc * 64 : (kc & (NCH / 2 - 1)) * 64;
        const char* pAh = (const char*)sAh + (size_t)(m0 + lrow) * 256 + aoff;
        const char* pAl = (const char*)sAl + (size_t)(m0 + lrow) * 256 + aoff;
        const char* pBh = (const char*)Bh + (size_t)lrow * (2 * K) + kc * 64;
        const char* pBl = (const char*)Bl + (size_t)lrow * (2 * K) + kc * 64;
        const uint32_t sb = us + buf * 32768;
        #pragma unroll
        for (int j = 0; j < 2; j++) {
            const int c16 = c16a + j;
            const uint32_t so = swz64((uint32_t)(lrow * 64 + c16 * 16));
            cp16(sb + so,          pAh + c16 * 16);
            cp16(sb + 8192 + so,   pAl + c16 * 16);
            cp16(sb + 16384 + so,  pBh + c16 * 16);
            cp16(sb + 24576 + so,  pBl + c16 * 16);
        }
        asm volatile("cp.async.commit_group;" ::: "memory");
    };

    issue(0, 0);
    for (int kc = 0; kc < NCH; kc++) {
        if (kc + 1 < NCH) {
            issue(kc + 1, (kc + 1) & 1);
            asm volatile("cp.async.wait_group 1;" ::: "memory");
        } else {
            asm volatile("cp.async.wait_group 0;" ::: "memory");
        }
        __syncthreads();
        const uint32_t sb = us + (kc & 1) * 32768;
        #pragma unroll
        for (int s = 0; s < 2; s++) {
            uint32_t aH[2][4], aL[2][4], bb[4][4];
            #pragma unroll
            for (int sub = 0; sub < 2; sub++) {
                const uint32_t off = swz64((uint32_t)(
                    (m0w + sub * 16 + (lane & 15)) * 64 + s * 32 + (lane >> 4) * 16));
                ldsm4(aH[sub], sb + off);
                ldsm4(aL[sub], sb + 8192 + off);
            }
            uint32_t offb[4];
            #pragma unroll
            for (int p = 0; p < 4; p++) {
                offb[p] = swz64((uint32_t)(
                    (n0w + p * 16 + (lane & 7) + ((lane >> 4) << 3)) * 64 +
                    s * 32 + ((lane >> 3) & 1) * 16));
                ldsm4(bb[p], sb + 16384 + offb[p]);
            }
            #pragma unroll
            for (int sub = 0; sub < 2; sub++)
                #pragma unroll
                for (int p = 0; p < 4; p++) {
                    mma16816(acc[sub][p * 2 + 0], aH[sub], &bb[p][0]);
                    mma16816(acc[sub][p * 2 + 1], aH[sub], &bb[p][2]);
                }
            #pragma unroll
            for (int sub = 0; sub < 2; sub++)
                #pragma unroll
                for (int p = 0; p < 4; p++) {
                    mma16816(acc[sub][p * 2 + 0], aL[sub], &bb[p][0]);
                    mma16816(acc[sub][p * 2 + 1], aL[sub], &bb[p][2]);
                }
            #pragma unroll
            for (int p = 0; p < 4; p++)
                ldsm4(bb[p], sb + 24576 + offb[p]);
            #pragma unroll
            for (int sub = 0; sub < 2; sub++)
                #pragma unroll
                for (int p = 0; p < 4; p++) {
                    mma16816(acc[sub][p * 2 + 0], aH[sub], &bb[p][0]);
                    mma16816(acc[sub][p * 2 + 1], aH[sub], &bb[p][2]);
                }
        }
        __syncthreads();
    }

    // ---------------- epilogue ----------------
    float al = 0.f, om = 0.f;
    if (MODE == 2) { al = *alphaPtr; om = 1.0f - al; }
    const int ccol0 = n0w + (lane & 3) * 2;
    #pragma unroll
    for (int sub = 0; sub < 2; sub++) {
        const int rbase = m0 + m0w + sub * 16 + (lane >> 2);
        #pragma unroll
        for (int f = 0; f < 8; f++) {
            const int col = ccol0 + f * 8;
            const float bx = bias[col], by = bias[col + 1];
            #pragma unroll
            for (int half = 0; half < 2; half++) {
                const int r = rbase + half * 8;
                if (r >= NN) continue;
                float vx = acc[sub][f][half * 2 + 0] + bx;
                float vy = acc[sub][f][half * 2 + 1] + by;
                if (MODE < 2) {
                    vx = fmaxf(vx, 0.f); vy = fmaxf(vy, 0.f);
                    __nv_bfloat162 h2, l2;
                    split1(vx, h2.x, l2.x); split1(vy, h2.y, l2.y);
                    *(__nv_bfloat162*)(outH + (size_t)r * C + col) = h2;
                    *(__nv_bfloat162*)(outL + (size_t)r * C + col) = l2;
                    if (MODE == 0)
                        *(__half2*)(outF16 + (size_t)r * C + col) = __floats2half2_rn(vx, vy);
                } else {
                    const float2 xr = *(const float2*)(xres + (size_t)r * C + col);
                    float2 fv;
                    fv.x = al * vx + om * xr.x;
                    fv.y = al * vy + om * xr.y;
                    *(float2*)(outF + (size_t)r * C + col) = fv;
                }
            }
        }
    }
}

// ---------------- launch ----------------
extern "C" void kernel_launch(void* const* d_in, const int* in_sizes, int n_in,
                              void* d_out, int out_size)
{
    const float* x    = (const float*)d_in[0];
    const int*   ei   = (const int*)  d_in[1];
    const float* W1l  = (const float*)d_in[2];
    const float* b1   = (const float*)d_in[3];
    const float* W1r  = (const float*)d_in[4];
    const float* W2l  = (const float*)d_in[5];
    const float* b2   = (const float*)d_in[6];
    const float* W2r  = (const float*)d_in[7];
    const float* Wd   = (const float*)d_in[8];
    const float* bd   = (const float*)d_in[9];
    const float* alph = (const float*)d_in[10];
    float* out = (float*)d_out;

    const int* src = ei;
    const int* dst = ei + NE;

    int* degp;
    __half *xf16, *h1f16;
    __nv_bfloat16 *xh, *xl, *aggh, *aggl, *h1h, *h1l, *h2h, *h2l;
    __nv_bfloat16 *w1h, *w1l, *w2h, *w2l, *wdh, *wdl;
    cudaGetSymbolAddress((void**)&degp, g_deg);
    cudaGetSymbolAddress((void**)&xf16, g_xf16);
    cudaGetSymbolAddress((void**)&h1f16,g_h1f16);
    cudaGetSymbolAddress((void**)&xh,   g_xh);
    cudaGetSymbolAddress((void**)&xl,   g_xl);
    cudaGetSymbolAddress((void**)&aggh, g_aggh);
    cudaGetSymbolAddress((void**)&aggl, g_aggl);
    cudaGetSymbolAddress((void**)&h1h,  g_h1h);
    cudaGetSymbolAddress((void**)&h1l,  g_h1l);
    cudaGetSymbolAddress((void**)&h2h,  g_h2h);
    cudaGetSymbolAddress((void**)&h2l,  g_h2l);
    cudaGetSymbolAddress((void**)&w1h,  g_w1h);
    cudaGetSymbolAddress((void**)&w1l,  g_w1l);
    cudaGetSymbolAddress((void**)&w2h,  g_w2h);
    cudaGetSymbolAddress((void**)&w2l,  g_w2l);
    cudaGetSymbolAddress((void**)&wdh,  g_wdh);
    cudaGetSymbolAddress((void**)&wdl,  g_wdl);

    static cudaStream_t s1 = nullptr;
    static cudaEvent_t ev0 = nullptr, evP = nullptr;
    if (s1 == nullptr) {
        cudaStreamCreateWithFlags(&s1, cudaStreamNonBlocking);
        cudaEventCreateWithFlags(&ev0, cudaEventDisableTiming);
        cudaEventCreateWithFlags(&evP, cudaEventDisableTiming);
    }

    const int SMEM_GEMM = 2 * 32768;
    static bool attrSet = false;
    if (!attrSet) {
        cudaFuncSetAttribute(gemm_mma_kernel<0>, cudaFuncAttributeMaxDynamicSharedMemorySize, SMEM_GEMM);
        cudaFuncSetAttribute(gemm_mma_kernel<1>, cudaFuncAttributeMaxDynamicSharedMemorySize, SMEM_GEMM);
        cudaFuncSetAttribute(gemm_mma_kernel<2>, cudaFuncAttributeMaxDynamicSharedMemorySize, SMEM_GEMM);
        attrSet = true;
    }

    const int TB = 256;
    const int gE  = (NE + TB - 1) / TB;
    const int gE4 = (NE / 4 + TB - 1) / TB;
    const int gAg = (NN * 32 + TB - 1) / TB;
    const int gM  = (NN + 127) / 128;
    const int gS  = (NN * C / 4 + TB - 1) / TB;
    const cudaStream_t s0 = (cudaStream_t)0;

    // fork: prep on s1, CSR on s0
    cudaEventRecord(ev0, s0);
    cudaStreamWaitEvent(s1, ev0, 0);

    split_kernel<<<gS, TB, 0, s1>>>(x, xh, xl, xf16);
    wprep_kernel<<<dim3(128, 3), 256, 0, s1>>>(W1l, W1r, W2l, W2r, Wd);
    cudaEventRecord(evP, s1);

    cudaMemsetAsync(degp, 0, NN * sizeof(int), s0);
    count_kernel<<<gE4, TB, 0, s0>>>((const int4*)dst);
    scan1_kernel<<<NB_SCAN, 1024, 0, s0>>>();
    scan2_kernel<<<1, 128, 0, s0>>>();
    scan3_kernel<<<NB_SCAN, 1024, 0, s0>>>();
    build_kernel<<<gE, TB, 0, s0>>>(src, dst);

    cudaStreamWaitEvent(s0, evP, 0);

    // layer 1
    agg_kernel<<<gAg, TB, 0, s0>>>(xf16);
    gemm_mma_kernel<0><<<gM, 256, SMEM_GEMM, s0>>>(aggh, aggl, xh, xl, w1h, w1l,
                                                   b1, nullptr, nullptr,
                                                   nullptr, h1f16, h1h, h1l);
    // layer 2
    agg_kernel<<<gAg, TB, 0, s0>>>(h1f16);
    gemm_mma_kernel<1><<<gM, 256, SMEM_GEMM, s0>>>(aggh, aggl, h1h, h1l, w2h, w2l,
                                                   b2, nullptr, nullptr,
                                                   nullptr, nullptr, h2h, h2l);
    // decoder + residual blend
    gemm_mma_kernel<2><<<gM, 256, SMEM_GEMM, s0>>>(h2h, h2l, nullptr, nullptr, wdh, wdl,
                                                   bd, x, alph,
                                                   out, nullptr, nullptr, nullptr);

    (void)in_sizes; (void)n_in; (void)out_size;
}

// round 8
// speedup vs baseline: 1.3389x; 1.3389x over previous
#include <cuda_runtime.h>
#include <cuda_fp16.h>
#include <cstdint>
#include <cstddef>

#define NN 100000
#define NPAD 100096   // 782 * 128
#define NE 1600000
#define C 128
#define NB_SCAN 98    // ceil(NN / 1024)

// ---------------- scratch (device globals) ----------------
__device__ int   g_deg[NN];
__device__ int   g_ptr[NN + 1];
__device__ int   g_cursor[NN];
__device__ float g_invc[NN];
__device__ int   g_csr[NE];
__device__ int   g_bsum[128];
__device__ float g_p1[(size_t)NPAD * C];

__device__ __half g_xf16 [(size_t)NPAD * C];
__device__ __half g_h1f16[(size_t)NPAD * C];
__device__ __half g_h2f16[(size_t)NPAD * C];
__device__ __half g_aggf16[(size_t)NPAD * C];

// weights fp16 hi/lo, [n][k] transposed
__device__ __half g_w1lh[128 * 128], g_w1ll[128 * 128];
__device__ __half g_w1rh[128 * 128], g_w1rl[128 * 128];
__device__ __half g_w2h [128 * 256], g_w2l [128 * 256];
__device__ __half g_wdh [128 * 128], g_wdl [128 * 128];

// ---------------- helpers ----------------
__device__ __forceinline__ uint32_t s2u(const void* p) {
    uint32_t a;
    asm("{ .reg .u64 t; cvta.to.shared.u64 t, %1; cvt.u32.u64 %0, t; }" : "=r"(a) : "l"(p));
    return a;
}
__device__ __forceinline__ void ldsm4(uint32_t* r, uint32_t addr) {
    asm volatile("ldmatrix.sync.aligned.m8n8.x4.shared.b16 {%0,%1,%2,%3}, [%4];"
                 : "=r"(r[0]), "=r"(r[1]), "=r"(r[2]), "=r"(r[3]) : "r"(addr));
}
__device__ __forceinline__ void mmaf16(float* d, const uint32_t* a, const uint32_t* b) {
    asm volatile(
        "mma.sync.aligned.m16n8k16.row.col.f32.f16.f16.f32 "
        "{%0,%1,%2,%3}, {%4,%5,%6,%7}, {%8,%9}, {%0,%1,%2,%3};"
        : "+f"(d[0]), "+f"(d[1]), "+f"(d[2]), "+f"(d[3])
        : "r"(a[0]), "r"(a[1]), "r"(a[2]), "r"(a[3]), "r"(b[0]), "r"(b[1]));
}
__device__ __forceinline__ uint32_t swz64(uint32_t off) {
    return off ^ ((off >> 3) & 0x30u);
}
__device__ __forceinline__ void cp16(uint32_t saddr, const void* gaddr) {
    asm volatile("cp.async.cg.shared.global [%0], [%1], 16;" :: "r"(saddr), "l"(gaddr));
}

// ---------------- CSR build ----------------
__global__ void zero_deg_kernel() {
    int i = blockIdx.x * blockDim.x + threadIdx.x;
    if (i < NN) g_deg[i] = 0;
}
__global__ void count_kernel(const int4* __restrict__ dst4) {
    int i = blockIdx.x * blockDim.x + threadIdx.x;
    if (i < NE / 4) {
        int4 d = dst4[i];
        atomicAdd(&g_deg[d.x], 1);
        atomicAdd(&g_deg[d.y], 1);
        atomicAdd(&g_deg[d.z], 1);
        atomicAdd(&g_deg[d.w], 1);
    }
}
__global__ void scan1_kernel() {
    __shared__ int wsum[32];
    const int lane = threadIdx.x & 31;
    const int wid  = threadIdx.x >> 5;
    int i = blockIdx.x * 1024 + threadIdx.x;
    int v = (i < NN) ? g_deg[i] : 0;
    int incl = v;
    #pragma unroll
    for (int o = 1; o < 32; o <<= 1) {
        int t = __shfl_up_sync(0xFFFFFFFFu, incl, o);
        if (lane >= o) incl += t;
    }
    if (lane == 31) wsum[wid] = incl;
    __syncthreads();
    if (wid == 0) {
        int ws = wsum[lane];
        int wi = ws;
        #pragma unroll
        for (int o = 1; o < 32; o <<= 1) {
            int t = __shfl_up_sync(0xFFFFFFFFu, wi, o);
            if (lane >= o) wi += t;
        }
        wsum[lane] = wi - ws;
    }
    __syncthreads();
    int excl = wsum[wid] + incl - v;
    if (i < NN) g_ptr[i] = excl;
    if (threadIdx.x == 1023) g_bsum[blockIdx.x] = excl + v;
}
__global__ void scan2_kernel() {
    __shared__ int ws[4];
    const int t = threadIdx.x;
    const int lane = t & 31;
    const int wid  = t >> 5;
    int v = (t < NB_SCAN) ? g_bsum[t] : 0;
    int incl = v;
    #pragma unroll
    for (int o = 1; o < 32; o <<= 1) {
        int s = __shfl_up_sync(0xFFFFFFFFu, incl, o);
        if (lane >= o) incl += s;
    }
    if (lane == 31) ws[wid] = incl;
    __syncthreads();
    int add = 0;
    #pragma unroll
    for (int w = 0; w < 4; w++) if (w < wid) add += ws[w];
    int excl = add + incl - v;
    __syncthreads();
    if (t < NB_SCAN) g_bsum[t] = excl;
}
__global__ void scan3_kernel() {
    int i = blockIdx.x * 1024 + threadIdx.x;
    if (i == 0) g_ptr[NN] = NE;
    if (i < NN) {
        g_ptr[i] += g_bsum[blockIdx.x];
        int d = g_deg[i];
        g_invc[i] = 1.0f / (float)(d < 1 ? 1 : d);
        g_cursor[i] = 0;
    }
}
__global__ void build_kernel(const int* __restrict__ src, const int* __restrict__ dst) {
    int e = blockIdx.x * blockDim.x + threadIdx.x;
    if (e < NE) {
        int d   = dst[e];
        int pos = atomicAdd(&g_cursor[d], 1);
        g_csr[g_ptr[d] + pos] = src[e];
    }
}

// ---------------- fp32 -> fp16 for x ----------------
__global__ void split_kernel(const float* __restrict__ in, __half* __restrict__ f16) {
    int i = blockIdx.x * blockDim.x + threadIdx.x;
    if (i < NN * C / 4) {
        float4 v = ((const float4*)in)[i];
        ((__half2*)f16)[i * 2]     = __floats2half2_rn(v.x, v.y);
        ((__half2*)f16)[i * 2 + 1] = __floats2half2_rn(v.z, v.w);
    }
}

// ---------------- weight prep: fp16 hi/lo, grid (128, 4) ----------------
__global__ void wprep_kernel(const float* __restrict__ W1l, const float* __restrict__ W1r,
                             const float* __restrict__ W2l, const float* __restrict__ W2r,
                             const float* __restrict__ Wd) {
    const int n = blockIdx.x;
    const int which = blockIdx.y;
    const float* Wa; const float* Wb; __half *bh, *bl; int K;
    if (which == 0)      { Wa = W1l; Wb = nullptr; bh = g_w1lh; bl = g_w1ll; K = 128; }
    else if (which == 1) { Wa = W1r; Wb = nullptr; bh = g_w1rh; bl = g_w1rl; K = 128; }
    else if (which == 2) { Wa = W2l; Wb = W2r;     bh = g_w2h;  bl = g_w2l;  K = 256; }
    else                 { Wa = Wd;  Wb = nullptr; bh = g_wdh;  bl = g_wdl;  K = 128; }
    for (int k = threadIdx.x; k < K; k += blockDim.x) {
        float v = (k < C) ? Wa[k * C + n] : Wb[(k - C) * C + n];
        __half h = __float2half_rn(v);
        __half l = __float2half_rn(v - __half2float(h));
        bh[n * K + k] = h;
        bl[n * K + k] = l;
    }
}

// ---------------- aggregation: warp per node, fp16 in/out ----------------
__global__ void agg_kernel(const __half* __restrict__ feat, __half* __restrict__ outp) {
    int gw = (blockIdx.x * blockDim.x + threadIdx.x) >> 5;
    if (gw >= NN) return;
    int lane = threadIdx.x & 31;
    int beg = g_ptr[gw], end = g_ptr[gw + 1];
    float4 acc = make_float4(0.f, 0.f, 0.f, 0.f);
    int e = beg;
    for (; e + 4 <= end; e += 4) {
        int s0 = g_csr[e], s1 = g_csr[e + 1], s2 = g_csr[e + 2], s3 = g_csr[e + 3];
        uint2 u0 = *reinterpret_cast<const uint2*>(feat + (size_t)s0 * C + lane * 4);
        uint2 u1 = *reinterpret_cast<const uint2*>(feat + (size_t)s1 * C + lane * 4);
        uint2 u2 = *reinterpret_cast<const uint2*>(feat + (size_t)s2 * C + lane * 4);
        uint2 u3 = *reinterpret_cast<const uint2*>(feat + (size_t)s3 * C + lane * 4);
        #pragma unroll
        for (int q = 0; q < 4; q++) {
            uint2 u = (q == 0) ? u0 : (q == 1) ? u1 : (q == 2) ? u2 : u3;
            float2 a = __half22float2(*(__half2*)&u.x);
            float2 b = __half22float2(*(__half2*)&u.y);
            acc.x += a.x; acc.y += a.y; acc.z += b.x; acc.w += b.y;
        }
    }
    for (; e < end; e++) {
        int s = g_csr[e];
        uint2 u = *reinterpret_cast<const uint2*>(feat + (size_t)s * C + lane * 4);
        float2 a = __half22float2(*(__half2*)&u.x);
        float2 b = __half22float2(*(__half2*)&u.y);
        acc.x += a.x; acc.y += a.y; acc.z += b.x; acc.w += b.y;
    }
    float iv = g_invc[gw];
    __half2 o0 = __floats2half2_rn(acc.x * iv, acc.y * iv);
    __half2 o1 = __floats2half2_rn(acc.z * iv, acc.w * iv);
    uint2 o; o.x = *(uint32_t*)&o0; o.y = *(uint32_t*)&o1;
    *reinterpret_cast<uint2*>(outp + (size_t)gw * C + lane * 4) = o;
}

// ---------------- fp16 2-product GEMM, cp.async pipelined ----------------
// D[128,128] = A[128,K] @ (Bh + Bl)^T, fp32 accum.
// MODE 0: R1      (K=128, A=x)        -> outF = acc
// MODE 1: L1      (K=128, A=agg)      -> relu(acc + P + bias) -> fp16
// MODE 2: layer2  (K=256, A1=agg,A2=h1) -> relu(acc + bias) -> fp16
// MODE 3: decoder (K=128, A=h2)       -> alpha*(acc+bias)+(1-alpha)*xres -> f32
// Stage layout: A[0,8K) Bh[8K,16K) Bl[16K,24K); 64B rows, swz64. 2 stages.
template <int MODE>
__global__ __launch_bounds__(256) void gemm_f16_kernel(
    const __half* __restrict__ A1, const __half* __restrict__ A2,
    const __half* __restrict__ Bh, const __half* __restrict__ Bl,
    const float* __restrict__ P, const float* __restrict__ bias,
    const float* __restrict__ xres, const float* __restrict__ alphaPtr,
    float* __restrict__ outF, __half* __restrict__ outH)
{
    constexpr int K    = (MODE == 2) ? 256 : 128;
    constexpr int NCH  = K / 32;
    constexpr int BROW = K * 2;     // bytes per B row
    constexpr int STG  = 24576;
    extern __shared__ __align__(128) char smem[];
    const uint32_t us = s2u(smem);

    const int tid  = threadIdx.x;
    const int wid  = tid >> 5;
    const int lane = tid & 31;
    const int m0   = blockIdx.x * 128;
    const int m0w  = (wid >> 1) * 32;
    const int n0w  = (wid & 1) * 64;

    const int lrow = tid >> 1;
    const int c16a = (tid & 1) * 2;

    float acc[2][8][4];
    #pragma unroll
    for (int i = 0; i < 2; i++)
        #pragma unroll
        for (int j = 0; j < 8; j++)
            #pragma unroll
            for (int q = 0; q < 4; q++) acc[i][j][q] = 0.f;

    auto issue = [&](int kc, int buf) {
        const __half* sA = (MODE == 2 && kc >= 4) ? A2 : A1;
        const char* pA  = (const char*)sA + (size_t)(m0 + lrow) * 256 + (kc & 3) * 64;
        const char* pBh = (const char*)Bh + (size_t)lrow * BROW + kc * 64;
        const char* pBl = (const char*)Bl + (size_t)lrow * BROW + kc * 64;
        const uint32_t sb = us + buf * STG;
        #pragma unroll
        for (int j = 0; j < 2; j++) {
            const int c16 = c16a + j;
            const uint32_t so = swz64((uint32_t)(lrow * 64 + c16 * 16));
            cp16(sb + so,          pA  + c16 * 16);
            cp16(sb + 8192 + so,   pBh + c16 * 16);
            cp16(sb + 16384 + so,  pBl + c16 * 16);
        }
        asm volatile("cp.async.commit_group;" ::: "memory");
    };

    issue(0, 0);
    for (int kc = 0; kc < NCH; kc++) {
        if (kc + 1 < NCH) {
            issue(kc + 1, (kc + 1) & 1);
            asm volatile("cp.async.wait_group 1;" ::: "memory");
        } else {
            asm volatile("cp.async.wait_group 0;" ::: "memory");
        }
        __syncthreads();
        const uint32_t sb = us + (kc & 1) * STG;
        #pragma unroll
        for (int s = 0; s < 2; s++) {
            uint32_t aF[2][4], bh[4][4], bl[4][4];
            #pragma unroll
            for (int sub = 0; sub < 2; sub++) {
                const uint32_t off = swz64((uint32_t)(
                    (m0w + sub * 16 + (lane & 15)) * 64 + s * 32 + (lane >> 4) * 16));
                ldsm4(aF[sub], sb + off);
            }
            uint32_t offb[4];
            #pragma unroll
            for (int p = 0; p < 4; p++) {
                offb[p] = swz64((uint32_t)(
                    (n0w + p * 16 + (lane & 7) + ((lane >> 4) << 3)) * 64 +
                    s * 32 + ((lane >> 3) & 1) * 16));
                ldsm4(bh[p], sb + 8192 + offb[p]);
                ldsm4(bl[p], sb + 16384 + offb[p]);
            }
            #pragma unroll
            for (int sub = 0; sub < 2; sub++)
                #pragma unroll
                for (int p = 0; p < 4; p++) {
                    mmaf16(acc[sub][p * 2 + 0], aF[sub], &bh[p][0]);
                    mmaf16(acc[sub][p * 2 + 1], aF[sub], &bh[p][2]);
                }
            #pragma unroll
            for (int sub = 0; sub < 2; sub++)
                #pragma unroll
                for (int p = 0; p < 4; p++) {
                    mmaf16(acc[sub][p * 2 + 0], aF[sub], &bl[p][0]);
                    mmaf16(acc[sub][p * 2 + 1], aF[sub], &bl[p][2]);
                }
        }
        __syncthreads();
    }

    // ---------------- epilogue ----------------
    float al = 0.f, om = 0.f;
    if (MODE == 3) { al = *alphaPtr; om = 1.0f - al; }
    const int ccol0 = n0w + (lane & 3) * 2;
    #pragma unroll
    for (int sub = 0; sub < 2; sub++) {
        const int rbase = m0 + m0w + sub * 16 + (lane >> 2);
        #pragma unroll
        for (int f = 0; f < 8; f++) {
            const int col = ccol0 + f * 8;
            float bx = 0.f, by = 0.f;
            if (MODE != 0) { bx = bias[col]; by = bias[col + 1]; }
            #pragma unroll
            for (int half = 0; half < 2; half++) {
                const int r = rbase + half * 8;
                if (r >= NN) continue;
                float vx = acc[sub][f][half * 2 + 0] + bx;
                float vy = acc[sub][f][half * 2 + 1] + by;
                if (MODE == 0) {
                    *(float2*)(outF + (size_t)r * C + col) = make_float2(vx, vy);
                } else if (MODE == 1 || MODE == 2) {
                    if (MODE == 1) {
                        const float2 pv = *(const float2*)(P + (size_t)r * C + col);
                        vx += pv.x; vy += pv.y;
                    }
                    vx = fmaxf(vx, 0.f); vy = fmaxf(vy, 0.f);
                    *(__half2*)(outH + (size_t)r * C + col) = __floats2half2_rn(vx, vy);
                } else {
                    const float2 xr = *(const float2*)(xres + (size_t)r * C + col);
                    float2 fv;
                    fv.x = al * vx + om * xr.x;
                    fv.y = al * vy + om * xr.y;
                    *(float2*)(outF + (size_t)r * C + col) = fv;
                }
            }
        }
    }
}

// ---------------- launch ----------------
extern "C" void kernel_launch(void* const* d_in, const int* in_sizes, int n_in,
                              void* d_out, int out_size)
{
    const float* x    = (const float*)d_in[0];
    const int*   ei   = (const int*)  d_in[1];
    const float* W1l  = (const float*)d_in[2];
    const float* b1   = (const float*)d_in[3];
    const float* W1r  = (const float*)d_in[4];
    const float* W2l  = (const float*)d_in[5];
    const float* b2   = (const float*)d_in[6];
    const float* W2r  = (const float*)d_in[7];
    const float* Wd   = (const float*)d_in[8];
    const float* bd   = (const float*)d_in[9];
    const float* alph = (const float*)d_in[10];
    float* out = (float*)d_out;

    const int* src = ei;
    const int* dst = ei + NE;

    float* p1;
    __half *xf16, *h1f16, *h2f16, *aggf16;
    __half *w1lh, *w1ll, *w1rh, *w1rl, *w2h, *w2l, *wdh, *wdl;
    cudaGetSymbolAddress((void**)&p1,    g_p1);
    cudaGetSymbolAddress((void**)&xf16,  g_xf16);
    cudaGetSymbolAddress((void**)&h1f16, g_h1f16);
    cudaGetSymbolAddress((void**)&h2f16, g_h2f16);
    cudaGetSymbolAddress((void**)&aggf16,g_aggf16);
    cudaGetSymbolAddress((void**)&w1lh,  g_w1lh);
    cudaGetSymbolAddress((void**)&w1ll,  g_w1ll);
    cudaGetSymbolAddress((void**)&w1rh,  g_w1rh);
    cudaGetSymbolAddress((void**)&w1rl,  g_w1rl);
    cudaGetSymbolAddress((void**)&w2h,   g_w2h);
    cudaGetSymbolAddress((void**)&w2l,   g_w2l);
    cudaGetSymbolAddress((void**)&wdh,   g_wdh);
    cudaGetSymbolAddress((void**)&wdl,   g_wdl);

    const int SMEM_GEMM = 2 * 24576;  // 48KB
    static bool attrSet = false;
    if (!attrSet) {
        cudaFuncSetAttribute(gemm_f16_kernel<0>, cudaFuncAttributeMaxDynamicSharedMemorySize, SMEM_GEMM);
        cudaFuncSetAttribute(gemm_f16_kernel<1>, cudaFuncAttributeMaxDynamicSharedMemorySize, SMEM_GEMM);
        cudaFuncSetAttribute(gemm_f16_kernel<2>, cudaFuncAttributeMaxDynamicSharedMemorySize, SMEM_GEMM);
        cudaFuncSetAttribute(gemm_f16_kernel<3>, cudaFuncAttributeMaxDynamicSharedMemorySize, SMEM_GEMM);
        attrSet = true;
    }

    const int TB = 256;
    const int gN  = (NN + TB - 1) / TB;
    const int gE  = (NE + TB - 1) / TB;
    const int gE4 = (NE / 4 + TB - 1) / TB;
    const int gAg = (NN * 32 + TB - 1) / TB;
    const int gM  = (NN + 127) / 128;
    const int gS  = (NN * C / 4 + TB - 1) / TB;

    // serial on default stream; launch #4 = gemm_f16<0> (for ncu slot)
    zero_deg_kernel<<<gN, TB>>>();                                       // 1
    split_kernel<<<gS, TB>>>(x, xf16);                                   // 2
    wprep_kernel<<<dim3(128, 4), 256>>>(W1l, W1r, W2l, W2r, Wd);         // 3
    gemm_f16_kernel<0><<<gM, 256, SMEM_GEMM>>>(xf16, nullptr, w1rh, w1rl,
                                               nullptr, nullptr, nullptr, nullptr,
                                               p1, nullptr);             // 4 <- profiled
    count_kernel<<<gE4, TB>>>((const int4*)dst);                         // 5
    scan1_kernel<<<NB_SCAN, 1024>>>();
    scan2_kernel<<<1, 128>>>();
    scan3_kernel<<<NB_SCAN, 1024>>>();
    build_kernel<<<gE, TB>>>(src, dst);

    // layer 1
    agg_kernel<<<gAg, TB>>>(xf16, aggf16);
    gemm_f16_kernel<1><<<gM, 256, SMEM_GEMM>>>(aggf16, nullptr, w1lh, w1ll,
                                               p1, b1, nullptr, nullptr,
                                               nullptr, h1f16);
    // layer 2 (fused K=256)
    agg_kernel<<<gAg, TB>>>(h1f16, aggf16);
    gemm_f16_kernel<2><<<gM, 256, SMEM_GEMM>>>(aggf16, h1f16, w2h, w2l,
                                               nullptr, b2, nullptr, nullptr,
                                               nullptr, h2f16);
    // decoder + residual blend
    gemm_f16_kernel<3><<<gM, 256, SMEM_GEMM>>>(h2f16, nullptr, wdh, wdl,
                                               nullptr, bd, x, alph,
                                               out, nullptr);

    (void)in_sizes; (void)n_in; (void)out_size;
}

// round 9
// speedup vs baseline: 1.5132x; 1.1302x over previous
#include <cuda_runtime.h>
#include <cuda_fp16.h>
#include <cstdint>
#include <cstddef>

#define NN 100000
#define NPAD 100096   // 782 * 128
#define NE 1600000
#define C 128
#define NB_SCAN 98    // ceil(NN / 1024)

// ---------------- scratch (device globals) ----------------
__device__ int   g_deg[NN];
__device__ int   g_ptr[NN + 1];
__device__ int   g_cursor[NN];
__device__ float g_invc[NN];
__device__ int   g_csr[NE];
__device__ int   g_bsum[128];

__device__ __half g_xf16 [(size_t)NPAD * C];
__device__ __half g_h1f16[(size_t)NPAD * C];
__device__ __half g_h2f16[(size_t)NPAD * C];
__device__ __half g_aggf16[(size_t)NPAD * C];

// weights fp16 hi/lo, [n][k] transposed; layer1/2 K=256 (Wl||Wr), decoder K=128
__device__ __half g_w1h[128 * 256], g_w1l[128 * 256];
__device__ __half g_w2h[128 * 256], g_w2l[128 * 256];
__device__ __half g_wdh[128 * 128], g_wdl[128 * 128];

// ---------------- helpers ----------------
__device__ __forceinline__ uint32_t s2u(const void* p) {
    uint32_t a;
    asm("{ .reg .u64 t; cvta.to.shared.u64 t, %1; cvt.u32.u64 %0, t; }" : "=r"(a) : "l"(p));
    return a;
}
__device__ __forceinline__ void ldsm4(uint32_t* r, uint32_t addr) {
    asm volatile("ldmatrix.sync.aligned.m8n8.x4.shared.b16 {%0,%1,%2,%3}, [%4];"
                 : "=r"(r[0]), "=r"(r[1]), "=r"(r[2]), "=r"(r[3]) : "r"(addr));
}
__device__ __forceinline__ void mmaf16(float* d, const uint32_t* a, const uint32_t* b) {
    asm volatile(
        "mma.sync.aligned.m16n8k16.row.col.f32.f16.f16.f32 "
        "{%0,%1,%2,%3}, {%4,%5,%6,%7}, {%8,%9}, {%0,%1,%2,%3};"
        : "+f"(d[0]), "+f"(d[1]), "+f"(d[2]), "+f"(d[3])
        : "r"(a[0]), "r"(a[1]), "r"(a[2]), "r"(a[3]), "r"(b[0]), "r"(b[1]));
}
__device__ __forceinline__ uint32_t swz64(uint32_t off) {
    return off ^ ((off >> 3) & 0x30u);
}
__device__ __forceinline__ void cp16(uint32_t saddr, const void* gaddr) {
    asm volatile("cp.async.cg.shared.global [%0], [%1], 16;" :: "r"(saddr), "l"(gaddr));
}

// ---------------- CSR build ----------------
__global__ void count_kernel(const int4* __restrict__ dst4) {
    int i = blockIdx.x * blockDim.x + threadIdx.x;
    if (i < NE / 4) {
        int4 d = dst4[i];
        atomicAdd(&g_deg[d.x], 1);
        atomicAdd(&g_deg[d.y], 1);
        atomicAdd(&g_deg[d.z], 1);
        atomicAdd(&g_deg[d.w], 1);
    }
}
__global__ void scan1_kernel() {
    __shared__ int wsum[32];
    const int lane = threadIdx.x & 31;
    const int wid  = threadIdx.x >> 5;
    int i = blockIdx.x * 1024 + threadIdx.x;
    int v = (i < NN) ? g_deg[i] : 0;
    int incl = v;
    #pragma unroll
    for (int o = 1; o < 32; o <<= 1) {
        int t = __shfl_up_sync(0xFFFFFFFFu, incl, o);
        if (lane >= o) incl += t;
    }
    if (lane == 31) wsum[wid] = incl;
    __syncthreads();
    if (wid == 0) {
        int ws = wsum[lane];
        int wi = ws;
        #pragma unroll
        for (int o = 1; o < 32; o <<= 1) {
            int t = __shfl_up_sync(0xFFFFFFFFu, wi, o);
            if (lane >= o) wi += t;
        }
        wsum[lane] = wi - ws;
    }
    __syncthreads();
    int excl = wsum[wid] + incl - v;
    if (i < NN) g_ptr[i] = excl;
    if (threadIdx.x == 1023) g_bsum[blockIdx.x] = excl + v;
}
__global__ void scan2_kernel() {
    __shared__ int ws[4];
    const int t = threadIdx.x;
    const int lane = t & 31;
    const int wid  = t >> 5;
    int v = (t < NB_SCAN) ? g_bsum[t] : 0;
    int incl = v;
    #pragma unroll
    for (int o = 1; o < 32; o <<= 1) {
        int s = __shfl_up_sync(0xFFFFFFFFu, incl, o);
        if (lane >= o) incl += s;
    }
    if (lane == 31) ws[wid] = incl;
    __syncthreads();
    int add = 0;
    #pragma unroll
    for (int w = 0; w < 4; w++) if (w < wid) add += ws[w];
    int excl = add + incl - v;
    __syncthreads();
    if (t < NB_SCAN) g_bsum[t] = excl;
}
__global__ void scan3_kernel() {
    int i = blockIdx.x * 1024 + threadIdx.x;
    if (i == 0) g_ptr[NN] = NE;
    if (i < NN) {
        g_ptr[i] += g_bsum[blockIdx.x];
        int d = g_deg[i];
        g_invc[i] = 1.0f / (float)(d < 1 ? 1 : d);
        g_cursor[i] = 0;
    }
}
__global__ void build_kernel(const int* __restrict__ src, const int* __restrict__ dst) {
    int e = blockIdx.x * blockDim.x + threadIdx.x;
    if (e < NE) {
        int d   = dst[e];
        int pos = atomicAdd(&g_cursor[d], 1);
        g_csr[g_ptr[d] + pos] = src[e];
    }
}

// ---------------- fp32 -> fp16 for x ----------------
__global__ void split_kernel(const float* __restrict__ in, __half* __restrict__ f16) {
    int i = blockIdx.x * blockDim.x + threadIdx.x;
    if (i < NN * C / 4) {
        float4 v = ((const float4*)in)[i];
        ((__half2*)f16)[i * 2]     = __floats2half2_rn(v.x, v.y);
        ((__half2*)f16)[i * 2 + 1] = __floats2half2_rn(v.z, v.w);
    }
}

// ---------------- weight prep: fp16 hi/lo, grid (128, 3) ----------------
__global__ void wprep_kernel(const float* __restrict__ W1l, const float* __restrict__ W1r,
                             const float* __restrict__ W2l, const float* __restrict__ W2r,
                             const float* __restrict__ Wd) {
    const int n = blockIdx.x;
    const int which = blockIdx.y;
    const float* Wa; const float* Wb; __half *bh, *bl; int K;
    if (which == 0)      { Wa = W1l; Wb = W1r;     bh = g_w1h; bl = g_w1l; K = 256; }
    else if (which == 1) { Wa = W2l; Wb = W2r;     bh = g_w2h; bl = g_w2l; K = 256; }
    else                 { Wa = Wd;  Wb = nullptr; bh = g_wdh; bl = g_wdl; K = 128; }
    for (int k = threadIdx.x; k < K; k += blockDim.x) {
        float v = (k < C) ? Wa[k * C + n] : Wb[(k - C) * C + n];
        __half h = __float2half_rn(v);
        __half l = __float2half_rn(v - __half2float(h));
        bh[n * K + k] = h;
        bl[n * K + k] = l;
    }
}

// ---------------- aggregation: warp per node, 8-edge MLP, fp16 in/out ----------------
__global__ void agg_kernel(const __half* __restrict__ feat, __half* __restrict__ outp) {
    int gw = (blockIdx.x * blockDim.x + threadIdx.x) >> 5;
    if (gw >= NN) return;
    int lane = threadIdx.x & 31;
    int beg = g_ptr[gw], end = g_ptr[gw + 1];
    float4 acc = make_float4(0.f, 0.f, 0.f, 0.f);
    int e = beg;
    for (; e + 8 <= end; e += 8) {
        int idx[8];
        #pragma unroll
        for (int j = 0; j < 8; j++) idx[j] = g_csr[e + j];
        uint2 u[8];
        #pragma unroll
        for (int j = 0; j < 8; j++)
            u[j] = *reinterpret_cast<const uint2*>(feat + (size_t)idx[j] * C + lane * 4);
        #pragma unroll
        for (int j = 0; j < 8; j++) {
            float2 a = __half22float2(*(__half2*)&u[j].x);
            float2 b = __half22float2(*(__half2*)&u[j].y);
            acc.x += a.x; acc.y += a.y; acc.z += b.x; acc.w += b.y;
        }
    }
    for (; e < end; e++) {
        int s = g_csr[e];
        uint2 uu = *reinterpret_cast<const uint2*>(feat + (size_t)s * C + lane * 4);
        float2 a = __half22float2(*(__half2*)&uu.x);
        float2 b = __half22float2(*(__half2*)&uu.y);
        acc.x += a.x; acc.y += a.y; acc.z += b.x; acc.w += b.y;
    }
    float iv = g_invc[gw];
    __half2 o0 = __floats2half2_rn(acc.x * iv, acc.y * iv);
    __half2 o1 = __floats2half2_rn(acc.z * iv, acc.w * iv);
    uint2 o; o.x = *(uint32_t*)&o0; o.y = *(uint32_t*)&o1;
    *reinterpret_cast<uint2*>(outp + (size_t)gw * C + lane * 4) = o;
}

// ---------------- fp16 2-product GEMM, 3-stage cp.async, 1 barrier/chunk ----------------
// D[128,128] = A[128,K] @ (Bh + Bl)^T, fp32 accum.
// MODE 0: layer   (K=256, A1=agg, A2=self) -> relu(acc + bias) -> fp16
// MODE 1: decoder (K=128, A1=h2)           -> alpha*(acc+bias)+(1-alpha)*xres -> f32
// Stage: A[0,8K) Bh[8K,16K) Bl[16K,24K); 64B rows, swz64; 3 stages (72KB).
template <int MODE>
__global__ __launch_bounds__(256, 2) void gemm_f16_kernel(
    const __half* __restrict__ A1, const __half* __restrict__ A2,
    const __half* __restrict__ Bh, const __half* __restrict__ Bl,
    const float* __restrict__ bias,
    const float* __restrict__ xres, const float* __restrict__ alphaPtr,
    float* __restrict__ outF, __half* __restrict__ outH)
{
    constexpr int K    = (MODE == 0) ? 256 : 128;
    constexpr int NCH  = K / 32;
    constexpr int BROW = K * 2;
    constexpr int STG  = 24576;
    extern __shared__ __align__(128) char smem[];
    const uint32_t us = s2u(smem);

    const int tid  = threadIdx.x;
    const int wid  = tid >> 5;
    const int lane = tid & 31;
    const int m0   = blockIdx.x * 128;
    const int m0w  = (wid >> 1) * 32;
    const int n0w  = (wid & 1) * 64;

    const int lrow = tid >> 1;
    const int c16a = (tid & 1) * 2;

    float acc[2][8][4];
    #pragma unroll
    for (int i = 0; i < 2; i++)
        #pragma unroll
        for (int j = 0; j < 8; j++)
            #pragma unroll
            for (int q = 0; q < 4; q++) acc[i][j][q] = 0.f;

    auto issue = [&](int kc, int buf) {
        const __half* sA = (MODE == 0 && kc >= 4) ? A2 : A1;
        const char* pA  = (const char*)sA + (size_t)(m0 + lrow) * 256 + (kc & 3) * 64;
        const char* pBh = (const char*)Bh + (size_t)lrow * BROW + kc * 64;
        const char* pBl = (const char*)Bl + (size_t)lrow * BROW + kc * 64;
        const uint32_t sb = us + buf * STG;
        #pragma unroll
        for (int j = 0; j < 2; j++) {
            const int c16 = c16a + j;
            const uint32_t so = swz64((uint32_t)(lrow * 64 + c16 * 16));
            cp16(sb + so,          pA  + c16 * 16);
            cp16(sb + 8192 + so,   pBh + c16 * 16);
            cp16(sb + 16384 + so,  pBl + c16 * 16);
        }
        asm volatile("cp.async.commit_group;" ::: "memory");
    };

    issue(0, 0);
    issue(1, 1);
    #pragma unroll
    for (int kc = 0; kc < NCH; kc++) {
        if (kc + 1 < NCH) {
            asm volatile("cp.async.wait_group 1;" ::: "memory");
        } else {
            asm volatile("cp.async.wait_group 0;" ::: "memory");
        }
        __syncthreads();
        if (kc + 2 < NCH) issue(kc + 2, (kc + 2) % 3);
        const uint32_t sb = us + (kc % 3) * STG;
        #pragma unroll
        for (int s = 0; s < 2; s++) {
            uint32_t aF[2][4], bh[4][4], bl[4][4];
            #pragma unroll
            for (int sub = 0; sub < 2; sub++) {
                const uint32_t off = swz64((uint32_t)(
                    (m0w + sub * 16 + (lane & 15)) * 64 + s * 32 + (lane >> 4) * 16));
                ldsm4(aF[sub], sb + off);
            }
            uint32_t offb[4];
            #pragma unroll
            for (int p = 0; p < 4; p++) {
                offb[p] = swz64((uint32_t)(
                    (n0w + p * 16 + (lane & 7) + ((lane >> 4) << 3)) * 64 +
                    s * 32 + ((lane >> 3) & 1) * 16));
                ldsm4(bh[p], sb + 8192 + offb[p]);
                ldsm4(bl[p], sb + 16384 + offb[p]);
            }
            #pragma unroll
            for (int sub = 0; sub < 2; sub++)
                #pragma unroll
                for (int p = 0; p < 4; p++) {
                    mmaf16(acc[sub][p * 2 + 0], aF[sub], &bh[p][0]);
                    mmaf16(acc[sub][p * 2 + 1], aF[sub], &bh[p][2]);
                }
            #pragma unroll
            for (int sub = 0; sub < 2; sub++)
                #pragma unroll
                for (int p = 0; p < 4; p++) {
                    mmaf16(acc[sub][p * 2 + 0], aF[sub], &bl[p][0]);
                    mmaf16(acc[sub][p * 2 + 1], aF[sub], &bl[p][2]);
                }
        }
    }

    // ---------------- epilogue ----------------
    float al = 0.f, om = 0.f;
    if (MODE == 1) { al = *alphaPtr; om = 1.0f - al; }
    const int ccol0 = n0w + (lane & 3) * 2;
    #pragma unroll
    for (int sub = 0; sub < 2; sub++) {
        const int rbase = m0 + m0w + sub * 16 + (lane >> 2);
        #pragma unroll
        for (int f = 0; f < 8; f++) {
            const int col = ccol0 + f * 8;
            const float bx = bias[col], by = bias[col + 1];
            #pragma unroll
            for (int half = 0; half < 2; half++) {
                const int r = rbase + half * 8;
                if (r >= NN) continue;
                float vx = acc[sub][f][half * 2 + 0] + bx;
                float vy = acc[sub][f][half * 2 + 1] + by;
                if (MODE == 0) {
                    vx = fmaxf(vx, 0.f); vy = fmaxf(vy, 0.f);
                    *(__half2*)(outH + (size_t)r * C + col) = __floats2half2_rn(vx, vy);
                } else {
                    const float2 xr = *(const float2*)(xres + (size_t)r * C + col);
                    float2 fv;
                    fv.x = al * vx + om * xr.x;
                    fv.y = al * vy + om * xr.y;
                    *(float2*)(outF + (size_t)r * C + col) = fv;
                }
            }
        }
    }
}

// ---------------- launch ----------------
extern "C" void kernel_launch(void* const* d_in, const int* in_sizes, int n_in,
                              void* d_out, int out_size)
{
    const float* x    = (const float*)d_in[0];
    const int*   ei   = (const int*)  d_in[1];
    const float* W1l  = (const float*)d_in[2];
    const float* b1   = (const float*)d_in[3];
    const float* W1r  = (const float*)d_in[4];
    const float* W2l  = (const float*)d_in[5];
    const float* b2   = (const float*)d_in[6];
    const float* W2r  = (const float*)d_in[7];
    const float* Wd   = (const float*)d_in[8];
    const float* bd   = (const float*)d_in[9];
    const float* alph = (const float*)d_in[10];
    float* out = (float*)d_out;

    const int* src = ei;
    const int* dst = ei + NE;

    int* degp;
    __half *xf16, *h1f16, *h2f16, *aggf16;
    __half *w1h, *w1l, *w2h, *w2l, *wdh, *wdl;
    cudaGetSymbolAddress((void**)&degp,  g_deg);
    cudaGetSymbolAddress((void**)&xf16,  g_xf16);
    cudaGetSymbolAddress((void**)&h1f16, g_h1f16);
    cudaGetSymbolAddress((void**)&h2f16, g_h2f16);
    cudaGetSymbolAddress((void**)&aggf16,g_aggf16);
    cudaGetSymbolAddress((void**)&w1h,   g_w1h);
    cudaGetSymbolAddress((void**)&w1l,   g_w1l);
    cudaGetSymbolAddress((void**)&w2h,   g_w2h);
    cudaGetSymbolAddress((void**)&w2l,   g_w2l);
    cudaGetSymbolAddress((void**)&wdh,   g_wdh);
    cudaGetSymbolAddress((void**)&wdl,   g_wdl);

    const int SMEM_GEMM = 3 * 24576;  // 72KB
    static bool attrSet = false;
    if (!attrSet) {
        cudaFuncSetAttribute(gemm_f16_kernel<0>, cudaFuncAttributeMaxDynamicSharedMemorySize, SMEM_GEMM);
        cudaFuncSetAttribute(gemm_f16_kernel<1>, cudaFuncAttributeMaxDynamicSharedMemorySize, SMEM_GEMM);
        attrSet = true;
    }

    const int TB = 256;
    const int gE  = (NE + TB - 1) / TB;
    const int gE4 = (NE / 4 + TB - 1) / TB;
    const int gAg = (NN * 32 + TB - 1) / TB;
    const int gM  = (NN + 127) / 128;
    const int gS  = (NN * C / 4 + TB - 1) / TB;

    cudaMemsetAsync(degp, 0, NN * sizeof(int));
    split_kernel<<<gS, TB>>>(x, xf16);
    wprep_kernel<<<dim3(128, 3), 256>>>(W1l, W1r, W2l, W2r, Wd);
    count_kernel<<<gE4, TB>>>((const int4*)dst);
    scan1_kernel<<<NB_SCAN, 1024>>>();
    scan2_kernel<<<1, 128>>>();
    scan3_kernel<<<NB_SCAN, 1024>>>();
    build_kernel<<<gE, TB>>>(src, dst);

    // layer 1 (fused K=256)
    agg_kernel<<<gAg, TB>>>(xf16, aggf16);
    gemm_f16_kernel<0><<<gM, 256, SMEM_GEMM>>>(aggf16, xf16, w1h, w1l,
                                               b1, nullptr, nullptr,
                                               nullptr, h1f16);
    // layer 2 (fused K=256)
    agg_kernel<<<gAg, TB>>>(h1f16, aggf16);
    gemm_f16_kernel<0><<<gM, 256, SMEM_GEMM>>>(aggf16, h1f16, w2h, w2l,
                                               b2, nullptr, nullptr,
                                               nullptr, h2f16);
    // decoder + residual blend
    gemm_f16_kernel<1><<<gM, 256, SMEM_GEMM>>>(h2f16, nullptr, wdh, wdl,
                                               bd, x, alph,
                                               out, nullptr);

    (void)in_sizes; (void)n_in; (void)out_size;
}

// round 10
// speedup vs baseline: 1.7994x; 1.1891x over previous
#include <cuda_runtime.h>
#include <cuda_fp16.h>
#include <cstdint>
#include <cstddef>

#define NN 100000
#define NPAD 100096   // 782 * 128
#define NE 1600000
#define C 128
#define NB_SCAN 98    // ceil(NN / 1024)

// ---------------- scratch (device globals) ----------------
__device__ int   g_deg[NN];
__device__ int   g_ptr[NN + 1];
__device__ int   g_cursor[NN];
__device__ float g_invc[NN];
__device__ int   g_csr[NE];
__device__ int   g_bsum[128];

__device__ __half g_xf16 [(size_t)NPAD * C];
__device__ __half g_h1f16[(size_t)NPAD * C];
__device__ __half g_h2f16[(size_t)NPAD * C];
__device__ __half g_aggf16[(size_t)NPAD * C];

// weights fp16, [n][k] transposed; layer1/2 K=256 (Wl||Wr), decoder K=128
__device__ __half g_w1[128 * 256];
__device__ __half g_w2[128 * 256];
__device__ __half g_wd[128 * 128];

// ---------------- helpers ----------------
__device__ __forceinline__ uint32_t s2u(const void* p) {
    uint32_t a;
    asm("{ .reg .u64 t; cvta.to.shared.u64 t, %1; cvt.u32.u64 %0, t; }" : "=r"(a) : "l"(p));
    return a;
}
__device__ __forceinline__ void ldsm4(uint32_t* r, uint32_t addr) {
    asm volatile("ldmatrix.sync.aligned.m8n8.x4.shared.b16 {%0,%1,%2,%3}, [%4];"
                 : "=r"(r[0]), "=r"(r[1]), "=r"(r[2]), "=r"(r[3]) : "r"(addr));
}
__device__ __forceinline__ void mmaf16(float* d, const uint32_t* a, const uint32_t* b) {
    asm volatile(
        "mma.sync.aligned.m16n8k16.row.col.f32.f16.f16.f32 "
        "{%0,%1,%2,%3}, {%4,%5,%6,%7}, {%8,%9}, {%0,%1,%2,%3};"
        : "+f"(d[0]), "+f"(d[1]), "+f"(d[2]), "+f"(d[3])
        : "r"(a[0]), "r"(a[1]), "r"(a[2]), "r"(a[3]), "r"(b[0]), "r"(b[1]));
}
__device__ __forceinline__ uint32_t swz64(uint32_t off) {
    return off ^ ((off >> 3) & 0x30u);
}
__device__ __forceinline__ void cp16(uint32_t saddr, const void* gaddr) {
    asm volatile("cp.async.cg.shared.global [%0], [%1], 16;" :: "r"(saddr), "l"(gaddr));
}

// ---------------- CSR build ----------------
__global__ void count_kernel(const int4* __restrict__ dst4) {
    int i = blockIdx.x * blockDim.x + threadIdx.x;
    if (i < NE / 4) {
        int4 d = dst4[i];
        atomicAdd(&g_deg[d.x], 1);
        atomicAdd(&g_deg[d.y], 1);
        atomicAdd(&g_deg[d.z], 1);
        atomicAdd(&g_deg[d.w], 1);
    }
}
__global__ void scan1_kernel() {
    __shared__ int wsum[32];
    const int lane = threadIdx.x & 31;
    const int wid  = threadIdx.x >> 5;
    int i = blockIdx.x * 1024 + threadIdx.x;
    int v = (i < NN) ? g_deg[i] : 0;
    int incl = v;
    #pragma unroll
    for (int o = 1; o < 32; o <<= 1) {
        int t = __shfl_up_sync(0xFFFFFFFFu, incl, o);
        if (lane >= o) incl += t;
    }
    if (lane == 31) wsum[wid] = incl;
    __syncthreads();
    if (wid == 0) {
        int ws = wsum[lane];
        int wi = ws;
        #pragma unroll
        for (int o = 1; o < 32; o <<= 1) {
            int t = __shfl_up_sync(0xFFFFFFFFu, wi, o);
            if (lane >= o) wi += t;
        }
        wsum[lane] = wi - ws;
    }
    __syncthreads();
    int excl = wsum[wid] + incl - v;
    if (i < NN) g_ptr[i] = excl;
    if (threadIdx.x == 1023) g_bsum[blockIdx.x] = excl + v;
}
__global__ void scan2_kernel() {
    __shared__ int ws[4];
    const int t = threadIdx.x;
    const int lane = t & 31;
    const int wid  = t >> 5;
    int v = (t < NB_SCAN) ? g_bsum[t] : 0;
    int incl = v;
    #pragma unroll
    for (int o = 1; o < 32; o <<= 1) {
        int s = __shfl_up_sync(0xFFFFFFFFu, incl, o);
        if (lane >= o) incl += s;
    }
    if (lane == 31) ws[wid] = incl;
    __syncthreads();
    int add = 0;
    #pragma unroll
    for (int w = 0; w < 4; w++) if (w < wid) add += ws[w];
    int excl = add + incl - v;
    __syncthreads();
    if (t < NB_SCAN) g_bsum[t] = excl;
}
__global__ void scan3_kernel() {
    int i = blockIdx.x * 1024 + threadIdx.x;
    if (i == 0) g_ptr[NN] = NE;
    if (i < NN) {
        g_ptr[i] += g_bsum[blockIdx.x];
        int d = g_deg[i];
        g_invc[i] = 1.0f / (float)(d < 1 ? 1 : d);
        g_cursor[i] = 0;
    }
}
__global__ void build_kernel(const int* __restrict__ src, const int* __restrict__ dst) {
    int e = blockIdx.x * blockDim.x + threadIdx.x;
    if (e < NE) {
        int d   = dst[e];
        int pos = atomicAdd(&g_cursor[d], 1);
        g_csr[g_ptr[d] + pos] = src[e];
    }
}

// ---------------- fp32 -> fp16 for x ----------------
__global__ void split_kernel(const float* __restrict__ in, __half* __restrict__ f16) {
    int i = blockIdx.x * blockDim.x + threadIdx.x;
    if (i < NN * C / 4) {
        float4 v = ((const float4*)in)[i];
        ((__half2*)f16)[i * 2]     = __floats2half2_rn(v.x, v.y);
        ((__half2*)f16)[i * 2 + 1] = __floats2half2_rn(v.z, v.w);
    }
}

// ---------------- weight prep: fp16, grid (128, 3) ----------------
__global__ void wprep_kernel(const float* __restrict__ W1l, const float* __restrict__ W1r,
                             const float* __restrict__ W2l, const float* __restrict__ W2r,
                             const float* __restrict__ Wd) {
    const int n = blockIdx.x;
    const int which = blockIdx.y;
    const float* Wa; const float* Wb; __half* bh; int K;
    if (which == 0)      { Wa = W1l; Wb = W1r;     bh = g_w1; K = 256; }
    else if (which == 1) { Wa = W2l; Wb = W2r;     bh = g_w2; K = 256; }
    else                 { Wa = Wd;  Wb = nullptr; bh = g_wd; K = 128; }
    for (int k = threadIdx.x; k < K; k += blockDim.x) {
        float v = (k < C) ? Wa[k * C + n] : Wb[(k - C) * C + n];
        bh[n * K + k] = __float2half_rn(v);
    }
}

// ---------------- aggregation: warp per node, 8-edge MLP, fp16 in/out ----------------
__global__ void agg_kernel(const __half* __restrict__ feat, __half* __restrict__ outp) {
    int gw = (blockIdx.x * blockDim.x + threadIdx.x) >> 5;
    if (gw >= NN) return;
    int lane = threadIdx.x & 31;
    int beg = g_ptr[gw], end = g_ptr[gw + 1];
    float4 acc = make_float4(0.f, 0.f, 0.f, 0.f);
    int e = beg;
    for (; e + 8 <= end; e += 8) {
        int idx[8];
        #pragma unroll
        for (int j = 0; j < 8; j++) idx[j] = g_csr[e + j];
        uint2 u[8];
        #pragma unroll
        for (int j = 0; j < 8; j++)
            u[j] = *reinterpret_cast<const uint2*>(feat + (size_t)idx[j] * C + lane * 4);
        #pragma unroll
        for (int j = 0; j < 8; j++) {
            float2 a = __half22float2(*(__half2*)&u[j].x);
            float2 b = __half22float2(*(__half2*)&u[j].y);
            acc.x += a.x; acc.y += a.y; acc.z += b.x; acc.w += b.y;
        }
    }
    for (; e < end; e++) {
        int s = g_csr[e];
        uint2 uu = *reinterpret_cast<const uint2*>(feat + (size_t)s * C + lane * 4);
        float2 a = __half22float2(*(__half2*)&uu.x);
        float2 b = __half22float2(*(__half2*)&uu.y);
        acc.x += a.x; acc.y += a.y; acc.z += b.x; acc.w += b.y;
    }
    float iv = g_invc[gw];
    __half2 o0 = __floats2half2_rn(acc.x * iv, acc.y * iv);
    __half2 o1 = __floats2half2_rn(acc.z * iv, acc.w * iv);
    uint2 o; o.x = *(uint32_t*)&o0; o.y = *(uint32_t*)&o1;
    *reinterpret_cast<uint2*>(outp + (size_t)gw * C + lane * 4) = o;
}

// ---------------- fp16 single-product GEMM, 3-stage cp.async, 1 barrier/chunk ----------------
// D[128,128] = A[128,K] @ B^T, fp32 accum.
// MODE 0: layer   (K=256, A1=agg, A2=self) -> relu(acc + bias) -> fp16
// MODE 1: decoder (K=128, A1=h2)           -> alpha*(acc+bias)+(1-alpha)*xres -> f32
// Stage: A[0,8K) B[8K,16K); 64B rows, swz64; 3 stages (48KB).
template <int MODE>
__global__ __launch_bounds__(256, 2) void gemm_f16_kernel(
    const __half* __restrict__ A1, const __half* __restrict__ A2,
    const __half* __restrict__ B,
    const float* __restrict__ bias,
    const float* __restrict__ xres, const float* __restrict__ alphaPtr,
    float* __restrict__ outF, __half* __restrict__ outH)
{
    constexpr int K    = (MODE == 0) ? 256 : 128;
    constexpr int NCH  = K / 32;
    constexpr int BROW = K * 2;
    constexpr int STG  = 16384;
    extern __shared__ __align__(128) char smem[];
    const uint32_t us = s2u(smem);

    const int tid  = threadIdx.x;
    const int wid  = tid >> 5;
    const int lane = tid & 31;
    const int m0   = blockIdx.x * 128;
    const int m0w  = (wid >> 1) * 32;
    const int n0w  = (wid & 1) * 64;

    const int lrow = tid >> 1;
    const int c16a = (tid & 1) * 2;

    float acc[2][8][4];
    #pragma unroll
    for (int i = 0; i < 2; i++)
        #pragma unroll
        for (int j = 0; j < 8; j++)
            #pragma unroll
            for (int q = 0; q < 4; q++) acc[i][j][q] = 0.f;

    auto issue = [&](int kc, int buf) {
        const __half* sA = (MODE == 0 && kc >= 4) ? A2 : A1;
        const char* pA = (const char*)sA + (size_t)(m0 + lrow) * 256 + (kc & 3) * 64;
        const char* pB = (const char*)B + (size_t)lrow * BROW + kc * 64;
        const uint32_t sb = us + buf * STG;
        #pragma unroll
        for (int j = 0; j < 2; j++) {
            const int c16 = c16a + j;
            const uint32_t so = swz64((uint32_t)(lrow * 64 + c16 * 16));
            cp16(sb + so,        pA + c16 * 16);
            cp16(sb + 8192 + so, pB + c16 * 16);
        }
        asm volatile("cp.async.commit_group;" ::: "memory");
    };

    issue(0, 0);
    issue(1, 1);
    #pragma unroll
    for (int kc = 0; kc < NCH; kc++) {
        if (kc + 1 < NCH) {
            asm volatile("cp.async.wait_group 1;" ::: "memory");
        } else {
            asm volatile("cp.async.wait_group 0;" ::: "memory");
        }
        __syncthreads();
        if (kc + 2 < NCH) issue(kc + 2, (kc + 2) % 3);
        const uint32_t sb = us + (kc % 3) * STG;
        #pragma unroll
        for (int s = 0; s < 2; s++) {
            uint32_t aF[2][4], bb[4][4];
            #pragma unroll
            for (int sub = 0; sub < 2; sub++) {
                const uint32_t off = swz64((uint32_t)(
                    (m0w + sub * 16 + (lane & 15)) * 64 + s * 32 + (lane >> 4) * 16));
                ldsm4(aF[sub], sb + off);
            }
            #pragma unroll
            for (int p = 0; p < 4; p++) {
                const uint32_t off = swz64((uint32_t)(
                    (n0w + p * 16 + (lane & 7) + ((lane >> 4) << 3)) * 64 +
                    s * 32 + ((lane >> 3) & 1) * 16));
                ldsm4(bb[p], sb + 8192 + off);
            }
            #pragma unroll
            for (int sub = 0; sub < 2; sub++)
                #pragma unroll
                for (int p = 0; p < 4; p++) {
                    mmaf16(acc[sub][p * 2 + 0], aF[sub], &bb[p][0]);
                    mmaf16(acc[sub][p * 2 + 1], aF[sub], &bb[p][2]);
                }
        }
    }

    // ---------------- epilogue ----------------
    float al = 0.f, om = 0.f;
    if (MODE == 1) { al = *alphaPtr; om = 1.0f - al; }
    const int ccol0 = n0w + (lane & 3) * 2;
    #pragma unroll
    for (int sub = 0; sub < 2; sub++) {
        const int rbase = m0 + m0w + sub * 16 + (lane >> 2);
        #pragma unroll
        for (int f = 0; f < 8; f++) {
            const int col = ccol0 + f * 8;
            const float bx = bias[col], by = bias[col + 1];
            #pragma unroll
            for (int half = 0; half < 2; half++) {
                const int r = rbase + half * 8;
                if (r >= NN) continue;
                float vx = acc[sub][f][half * 2 + 0] + bx;
                float vy = acc[sub][f][half * 2 + 1] + by;
                if (MODE == 0) {
                    vx = fmaxf(vx, 0.f); vy = fmaxf(vy, 0.f);
                    *(__half2*)(outH + (size_t)r * C + col) = __floats2half2_rn(vx, vy);
                } else {
                    const float2 xr = *(const float2*)(xres + (size_t)r * C + col);
                    float2 fv;
                    fv.x = al * vx + om * xr.x;
                    fv.y = al * vy + om * xr.y;
                    *(float2*)(outF + (size_t)r * C + col) = fv;
                }
            }
        }
    }
}

// ---------------- launch ----------------
extern "C" void kernel_launch(void* const* d_in, const int* in_sizes, int n_in,
                              void* d_out, int out_size)
{
    const float* x    = (const float*)d_in[0];
    const int*   ei   = (const int*)  d_in[1];
    const float* W1l  = (const float*)d_in[2];
    const float* b1   = (const float*)d_in[3];
    const float* W1r  = (const float*)d_in[4];
    const float* W2l  = (const float*)d_in[5];
    const float* b2   = (const float*)d_in[6];
    const float* W2r  = (const float*)d_in[7];
    const float* Wd   = (const float*)d_in[8];
    const float* bd   = (const float*)d_in[9];
    const float* alph = (const float*)d_in[10];
    float* out = (float*)d_out;

    const int* src = ei;
    const int* dst = ei + NE;

    int* degp;
    __half *xf16, *h1f16, *h2f16, *aggf16;
    __half *w1, *w2, *wd;
    cudaGetSymbolAddress((void**)&degp,  g_deg);
    cudaGetSymbolAddress((void**)&xf16,  g_xf16);
    cudaGetSymbolAddress((void**)&h1f16, g_h1f16);
    cudaGetSymbolAddress((void**)&h2f16, g_h2f16);
    cudaGetSymbolAddress((void**)&aggf16,g_aggf16);
    cudaGetSymbolAddress((void**)&w1,    g_w1);
    cudaGetSymbolAddress((void**)&w2,    g_w2);
    cudaGetSymbolAddress((void**)&wd,    g_wd);

    const int SMEM_GEMM = 3 * 16384;  // 48KB
    static bool attrSet = false;
    if (!attrSet) {
        cudaFuncSetAttribute(gemm_f16_kernel<0>, cudaFuncAttributeMaxDynamicSharedMemorySize, SMEM_GEMM);
        cudaFuncSetAttribute(gemm_f16_kernel<1>, cudaFuncAttributeMaxDynamicSharedMemorySize, SMEM_GEMM);
        attrSet = true;
    }

    const int TB = 256;
    const int gE  = (NE + TB - 1) / TB;
    const int gE4 = (NE / 4 + TB - 1) / TB;
    const int gAg = (NN * 32 + TB - 1) / TB;
    const int gM  = (NN + 127) / 128;
    const int gS  = (NN * C / 4 + TB - 1) / TB;

    cudaMemsetAsync(degp, 0, NN * sizeof(int));
    split_kernel<<<gS, TB>>>(x, xf16);
    wprep_kernel<<<dim3(128, 3), 256>>>(W1l, W1r, W2l, W2r, Wd);
    count_kernel<<<gE4, TB>>>((const int4*)dst);
    scan1_kernel<<<NB_SCAN, 1024>>>();
    scan2_kernel<<<1, 128>>>();
    scan3_kernel<<<NB_SCAN, 1024>>>();
    build_kernel<<<gE, TB>>>(src, dst);

    // layer 1 (fused K=256)
    agg_kernel<<<gAg, TB>>>(xf16, aggf16);
    gemm_f16_kernel<0><<<gM, 256, SMEM_GEMM>>>(aggf16, xf16, w1,
                                               b1, nullptr, nullptr,
                                               nullptr, h1f16);
    // layer 2 (fused K=256)
    agg_kernel<<<gAg, TB>>>(h1f16, aggf16);
    gemm_f16_kernel<0><<<gM, 256, SMEM_GEMM>>>(aggf16, h1f16, w2,
                                               b2, nullptr, nullptr,
                                               nullptr, h2f16);
    // decoder + residual blend
    gemm_f16_kernel<1><<<gM, 256, SMEM_GEMM>>>(h2f16, nullptr, wd,
                                               bd, x, alph,
                                               out, nullptr);

    (void)in_sizes; (void)n_in; (void)out_size;
}